// round 13
// baseline (speedup 1.0000x reference)
#include <cuda_runtime.h>
#include <cuda_bf16.h>
#include <math.h>
#include <stdint.h>

#define BB 64
#define TT 64
#define AA 64
#define HH 1024
#define CC 16

#define NT 128     // N cols per CTA
#define KC 32      // K floats per chunk

#define KSPLIT 32
#define TAU_KB (HH / KSPLIT)   // 32

// mma kernel dynamic smem layout (bytes)
#define A_PL   5120                    // 64 rows * 80 B
#define B_PL   8704                    // 32 rows * 272 B
#define BUF_SZ (2 * A_PL + 2 * B_PL)   // 27648
#define SMEM_SZ (2 * BUF_SZ)           // 55296

// Scratch (device globals; no runtime allocation)
__device__ __align__(16) __nv_bfloat16 g_a0h[BB * TT * AA], g_a0l[BB * TT * AA];
__device__ __align__(16) __nv_bfloat16 g_a1h[BB * TT * HH], g_a1l[BB * TT * HH];
__device__ __align__(16) __nv_bfloat16 g_a2h[BB * TT * HH], g_a2l[BB * TT * HH];
// Weight planes
__device__ __align__(16) __nv_bfloat16 g_w1h[CC * AA * HH], g_w1l[CC * AA * HH];
__device__ __align__(16) __nv_bfloat16 g_w2h[CC * HH * HH], g_w2l[CC * HH * HH];
__device__ __align__(16) __nv_bfloat16 g_w3h[CC * HH * HH], g_w3l[CC * HH * HH];
__device__ float g_tauc[BB * HH];
__device__ float g_tau[BB * HH];
__device__ float g_part[KSPLIT * BB * HH];
__device__ int   g_cat_cnt[CC];
__device__ int   g_cat_list[CC * BB];

// ---------------- helpers ----------------
__device__ __forceinline__ uint32_t smem_u32(const void* p) {
    uint32_t a;
    asm("{ .reg .u64 t; cvta.to.shared.u64 t, %1; cvt.u32.u64 %0, t; }"
        : "=r"(a) : "l"(p));
    return a;
}
__device__ __forceinline__ void split_pair(float x, float y, uint32_t& h, uint32_t& l) {
    __nv_bfloat162 hb = __floats2bfloat162_rn(x, y);   // low 16 = x
    float hx = __bfloat162float(hb.x);
    float hy = __bfloat162float(hb.y);
    __nv_bfloat162 lb = __floats2bfloat162_rn(x - hx, y - hy);
    h = *reinterpret_cast<uint32_t*>(&hb);
    l = *reinterpret_cast<uint32_t*>(&lb);
}
__device__ __forceinline__ void mma_bf16(float* c, const uint32_t* a, uint32_t b0, uint32_t b1) {
    asm volatile(
        "mma.sync.aligned.m16n8k16.row.col.f32.bf16.bf16.f32 "
        "{%0,%1,%2,%3}, {%4,%5,%6,%7}, {%8,%9}, {%0,%1,%2,%3};"
        : "+f"(c[0]), "+f"(c[1]), "+f"(c[2]), "+f"(c[3])
        : "r"(a[0]), "r"(a[1]), "r"(a[2]), "r"(a[3]), "r"(b0), "r"(b1));
}
__device__ __forceinline__ void ldsm_x4(uint32_t* r, uint32_t addr) {
    asm volatile("ldmatrix.sync.aligned.m8n8.x4.shared.b16 {%0,%1,%2,%3}, [%4];"
                 : "=r"(r[0]), "=r"(r[1]), "=r"(r[2]), "=r"(r[3]) : "r"(addr));
}
__device__ __forceinline__ void ldsm_x4_t(uint32_t* r, uint32_t addr) {
    asm volatile("ldmatrix.sync.aligned.m8n8.x4.trans.shared.b16 {%0,%1,%2,%3}, [%4];"
                 : "=r"(r[0]), "=r"(r[1]), "=r"(r[2]), "=r"(r[3]) : "r"(addr));
}
__device__ __forceinline__ void cp_async16(uint32_t s, const void* g) {
    asm volatile("cp.async.ca.shared.global [%0], [%1], 16;" :: "r"(s), "l"(g));
}
#define CP_COMMIT() asm volatile("cp.async.commit_group;" ::: "memory")
#define CP_WAIT(n)  asm volatile("cp.async.wait_group %0;" :: "n"(n) : "memory")

// ---------------------------------------------------------------------------
// prep: bucket batches by category (for tau2)
// ---------------------------------------------------------------------------
__global__ void prep_kernel(const int* __restrict__ cat_ids) {
    int c = threadIdx.x;
    if (c >= CC) return;
    int cnt = 0;
    for (int b = 0; b < BB; ++b)
        if (cat_ids[b] == c) g_cat_list[c * BB + cnt++] = b;
    g_cat_cnt[c] = cnt;
}

// ---------------------------------------------------------------------------
// wconv: fp32 weights -> bf16 hi/lo planes. grid(64, CC), 256 thr.
// ---------------------------------------------------------------------------
__global__ void wconv_kernel(const float* __restrict__ src,
                             __nv_bfloat16* __restrict__ dh,
                             __nv_bfloat16* __restrict__ dl,
                             size_t src_cat_stride, size_t dst_cat_stride,
                             int npairs) {
    const int cat = blockIdx.y;
    const float2* s = (const float2*)(src + cat * src_cat_stride);
    uint32_t* oh = (uint32_t*)(dh + cat * dst_cat_stride);
    uint32_t* ol = (uint32_t*)(dl + cat * dst_cat_stride);
    for (int i = blockIdx.x * 256 + threadIdx.x; i < npairs; i += 64 * 256) {
        float2 v = s[i];
        uint32_t h, l;
        split_pair(v.x, v.y, h, l);
        oh[i] = h;
        ol[i] = l;
    }
}

// ---------------------------------------------------------------------------
// actconv: actions fp32 -> bf16 hi/lo planes
// ---------------------------------------------------------------------------
__global__ void actconv_kernel(const float* __restrict__ actions) {
    int i = blockIdx.x * 512 + threadIdx.x;    // pair index
    float x = actions[2 * i], y = actions[2 * i + 1];
    uint32_t h, l;
    split_pair(x, y, h, l);
    ((uint32_t*)g_a0h)[i] = h;
    ((uint32_t*)g_a0l)[i] = l;
}

// ---------------------------------------------------------------------------
// tau1: per-batch sinusoidal embedding vector (1024)
// ---------------------------------------------------------------------------
__global__ void tau1_kernel(const int* __restrict__ timesteps) {
    const int b = blockIdx.x;
    const int tid = threadIdx.x;
    const float t = (float)timesteps[b];
    const int half = HH / 2;
    const float scale = logf(10000.0f) / (float)half;
    for (int d = tid; d < HH; d += 256) {
        int j = (d < half) ? d : (d - half);
        float f = t * expf(-(float)j * scale);
        g_tau[b * HH + d] = (d < half) ? sinf(f) : cosf(f);
    }
}

// ---------------------------------------------------------------------------
// tau2: cat-grouped, K-split matvec partials
// grid(HH/2/128, CC, KSPLIT), 128 threads, float2 loads.
// ---------------------------------------------------------------------------
__global__ void tau2_kernel(const float* __restrict__ W2) {
    const int cat = blockIdx.y;
    const int z   = blockIdx.z;
    const int tid = threadIdx.x;
    const int n2  = blockIdx.x * 128 + tid;
    const int cnt = g_cat_cnt[cat];
    if (cnt == 0) return;

    __shared__ float ts[8][TAU_KB];
    const int k0 = z * TAU_KB;
    const float* Wp = W2 + (size_t)cat * 2 * HH * HH
                         + (size_t)(HH + k0) * HH + 2 * n2;

    for (int base = 0; base < cnt; base += 8) {
        int nb = min(8, cnt - base);
        __syncthreads();
        for (int bl = 0; bl < nb; ++bl) {
            int bb = g_cat_list[cat * BB + base + bl];
            for (int d = tid; d < TAU_KB; d += 128)
                ts[bl][d] = g_tau[bb * HH + k0 + d];
        }
        __syncthreads();
        float2 acc[8];
        #pragma unroll
        for (int bl = 0; bl < 8; ++bl) acc[bl] = make_float2(0.f, 0.f);
        #pragma unroll 4
        for (int k = 0; k < TAU_KB; ++k) {
            float2 w = *(const float2*)&Wp[(size_t)k * HH];
            #pragma unroll
            for (int bl = 0; bl < 8; ++bl) {
                acc[bl].x = fmaf(ts[bl][k], w.x, acc[bl].x);
                acc[bl].y = fmaf(ts[bl][k], w.y, acc[bl].y);
            }
        }
        for (int bl = 0; bl < nb; ++bl) {
            int bb = g_cat_list[cat * BB + base + bl];
            *(float2*)&g_part[((size_t)z * BB + bb) * HH + 2 * n2] = acc[bl];
        }
    }
}

// ---------------------------------------------------------------------------
// tau3: deterministic reduce of partials + bias -> g_tauc
// ---------------------------------------------------------------------------
__global__ void tau3_kernel(const int* __restrict__ cat_ids,
                            const float* __restrict__ b2) {
    const int b = blockIdx.y;
    const int n = blockIdx.x * 256 + threadIdx.x;
    const int c = cat_ids[b];
    float s = b2[c * HH + n];
    #pragma unroll
    for (int z = 0; z < KSPLIT; ++z)
        s += g_part[((size_t)z * BB + b) * HH + n];
    g_tauc[b * HH + n] = s;
}

// ---------------------------------------------------------------------------
// Split-bf16 mma.sync GEMM layer v2: all operands pre-split bf16 planes.
// Pure cp.async staging (no convert, no prefetch regs), double-buffered.
// grid(HH/NT, BB), 256 threads (2m x 4n warps, 32x32 each).
//   out[b] = act( A[b](64 x K) @ W[cat[b]](K x 1024) + addend )
// OUTMODE 0: fp32 out; OUTMODE 1: bf16 hi/lo planes.
// ---------------------------------------------------------------------------
template <int K, int ACT, int ADDMODE, int OUTMODE>
__global__ void __launch_bounds__(256, 3)
mma_layer(const __nv_bfloat16* __restrict__ Ahp,
          const __nv_bfloat16* __restrict__ Alp,
          const __nv_bfloat16* __restrict__ Whp,
          const __nv_bfloat16* __restrict__ Wlp,
          size_t wstride,
          const float* __restrict__ addv,
          const int* __restrict__ cat_ids,
          float* __restrict__ outf,
          __nv_bfloat16* __restrict__ outh,
          __nv_bfloat16* __restrict__ outl) {
    extern __shared__ char sm[];
    const uint32_t smb = smem_u32(sm);

    const int tid  = threadIdx.x;
    const int lane = tid & 31;
    const int warp = tid >> 5;
    const int wm   = warp >> 2;   // 0..1
    const int wn   = warp & 3;    // 0..3
    const int b    = blockIdx.y;
    const int nt   = blockIdx.x;
    const int c    = cat_ids[b];

    const __nv_bfloat16* Ap[2] = {Ahp + (size_t)b * 64 * K,
                                  Alp + (size_t)b * 64 * K};
    const __nv_bfloat16* Wp[2] = {Whp + (size_t)c * wstride + nt * NT,
                                  Wlp + (size_t)c * wstride + nt * NT};

    float acc[2][4][4];
    #pragma unroll
    for (int i = 0; i < 2; ++i)
        #pragma unroll
        for (int j = 0; j < 4; ++j)
            #pragma unroll
            for (int q = 0; q < 4; ++q) acc[i][j][q] = 0.0f;

    constexpr int NCHUNK = K / KC;

    // cp.async staging for one chunk into buffer `buf`:
    // A: 512 16B items (2 planes x 64 rows x 4/row): i = tid + 256r, r<2
    // B: 1024 16B items (2 planes x 32 rows x 16/row): i = tid + 256r, r<4
    auto issue = [&](int k0, int buf) {
        const uint32_t base = smb + buf * BUF_SZ;
        #pragma unroll
        for (int r = 0; r < 2; ++r) {
            int i = tid + r * 256;
            int p = i >> 8, rem = i & 255, m = rem >> 2, it = rem & 3;
            cp_async16(base + p * A_PL + m * 80 + it * 16,
                       Ap[p] + (size_t)m * K + k0 + it * 8);
        }
        #pragma unroll
        for (int r = 0; r < 4; ++r) {
            int i = tid + r * 256;
            int p = i >> 9, rem = i & 511, k = rem >> 4, it = rem & 15;
            cp_async16(base + 2 * A_PL + p * B_PL + k * 272 + it * 16,
                       Wp[p] + (size_t)(k0 + k) * HH + it * 8);
        }
    };

    const int l15 = lane & 15, g16 = lane >> 4;

    issue(0, 0); CP_COMMIT();

    for (int ch = 0; ch < NCHUNK; ++ch) {
        const int cur = ch & 1;
        if (ch + 1 < NCHUNK) {
            issue((ch + 1) * KC, cur ^ 1); CP_COMMIT();
            CP_WAIT(1);                    // chunk ch resident
        } else {
            CP_WAIT(0);
        }
        __syncthreads();

        // ---- MMA phase on buffer cur ----
        const uint32_t aHi = smb + cur * BUF_SZ;
        const uint32_t aLo = aHi + A_PL;
        const uint32_t bHi = aHi + 2 * A_PL;
        const uint32_t bLo = bHi + B_PL;
        #pragma unroll
        for (int t = 0; t < 2; ++t) {
            uint32_t Ahf[2][4], Alf[2][4];
            #pragma unroll
            for (int ms = 0; ms < 2; ++ms) {
                uint32_t abyte = (wm * 32 + ms * 16 + l15) * 80 + t * 32 + g16 * 16;
                ldsm_x4(Ahf[ms], aHi + abyte);
                ldsm_x4(Alf[ms], aLo + abyte);
            }
            uint32_t Bh[2][4], Bl[2][4];
            #pragma unroll
            for (int nfp = 0; nfp < 2; ++nfp) {
                int kr = t * 16 + l15;
                uint32_t bbyte = kr * 272 + (wn * 32 + nfp * 16 + g16 * 8) * 2;
                ldsm_x4_t(Bh[nfp], bHi + bbyte);
                ldsm_x4_t(Bl[nfp], bLo + bbyte);
            }
            #pragma unroll
            for (int nf = 0; nf < 4; ++nf) {
                uint32_t bh0 = Bh[nf >> 1][(nf & 1) * 2];
                uint32_t bh1 = Bh[nf >> 1][(nf & 1) * 2 + 1];
                uint32_t bl0 = Bl[nf >> 1][(nf & 1) * 2];
                uint32_t bl1 = Bl[nf >> 1][(nf & 1) * 2 + 1];
                #pragma unroll
                for (int ms = 0; ms < 2; ++ms) {
                    mma_bf16(acc[ms][nf], Ahf[ms], bh0, bh1);   // hi*hi
                    mma_bf16(acc[ms][nf], Ahf[ms], bl0, bl1);   // hi*lo
                    mma_bf16(acc[ms][nf], Alf[ms], bh0, bh1);   // lo*hi
                }
            }
        }
        __syncthreads();   // all warps done reading buffer cur
    }

    // ---- epilogue ----
    const float* addp = (ADDMODE == 0) ? (addv + (size_t)c * HH)
                                       : (addv + (size_t)b * HH);
    const int lr = lane >> 2;
    const int lc = lane & 3;
    #pragma unroll
    for (int ms = 0; ms < 2; ++ms) {
        int r0 = wm * 32 + ms * 16 + lr;
        #pragma unroll
        for (int nf = 0; nf < 4; ++nf) {
            int ncol = nt * NT + wn * 32 + nf * 8 + lc * 2;
            float bv0 = addp[ncol], bv1 = addp[ncol + 1];
            float v0 = acc[ms][nf][0] + bv0;
            float v1 = acc[ms][nf][1] + bv1;
            float v2 = acc[ms][nf][2] + bv0;
            float v3 = acc[ms][nf][3] + bv1;
            if (ACT == 1) {
                v0 = v0 / (1.0f + expf(-v0));
                v1 = v1 / (1.0f + expf(-v1));
                v2 = v2 / (1.0f + expf(-v2));
                v3 = v3 / (1.0f + expf(-v3));
            }
            size_t o0 = ((size_t)b * TT + r0)     * HH + ncol;
            size_t o1 = ((size_t)b * TT + r0 + 8) * HH + ncol;
            if (OUTMODE == 0) {
                *(float2*)&outf[o0] = make_float2(v0, v1);
                *(float2*)&outf[o1] = make_float2(v2, v3);
            } else {
                uint32_t h, l;
                split_pair(v0, v1, h, l);
                *(uint32_t*)&outh[o0] = h;
                *(uint32_t*)&outl[o0] = l;
                split_pair(v2, v3, h, l);
                *(uint32_t*)&outh[o1] = h;
                *(uint32_t*)&outl[o1] = l;
            }
        }
    }
}

extern "C" void kernel_launch(void* const* d_in, const int* in_sizes, int n_in,
                              void* d_out, int out_size) {
    const float* actions   = (const float*)d_in[0];
    const int*   timesteps = (const int*)d_in[1];
    const int*   cat_ids   = (const int*)d_in[2];
    const float* W1 = (const float*)d_in[3];
    const float* b1 = (const float*)d_in[4];
    const float* W2 = (const float*)d_in[5];
    const float* b2 = (const float*)d_in[6];
    const float* W3 = (const float*)d_in[7];
    const float* b3 = (const float*)d_in[8];
    float* out = (float*)d_out;

    __nv_bfloat16 *a0h, *a0l, *a1h, *a1l, *a2h, *a2l;
    __nv_bfloat16 *w1h, *w1l, *w2h, *w2l, *w3h, *w3l;
    float *tauc;
    cudaGetSymbolAddress((void**)&a0h, g_a0h);
    cudaGetSymbolAddress((void**)&a0l, g_a0l);
    cudaGetSymbolAddress((void**)&a1h, g_a1h);
    cudaGetSymbolAddress((void**)&a1l, g_a1l);
    cudaGetSymbolAddress((void**)&a2h, g_a2h);
    cudaGetSymbolAddress((void**)&a2l, g_a2l);
    cudaGetSymbolAddress((void**)&w1h, g_w1h);
    cudaGetSymbolAddress((void**)&w1l, g_w1l);
    cudaGetSymbolAddress((void**)&w2h, g_w2h);
    cudaGetSymbolAddress((void**)&w2l, g_w2l);
    cudaGetSymbolAddress((void**)&w3h, g_w3h);
    cudaGetSymbolAddress((void**)&w3l, g_w3l);
    cudaGetSymbolAddress((void**)&tauc, g_tauc);

    cudaFuncSetAttribute(mma_layer<AA, 0, 0, 1>,
                         cudaFuncAttributeMaxDynamicSharedMemorySize, SMEM_SZ);
    cudaFuncSetAttribute(mma_layer<HH, 1, 1, 1>,
                         cudaFuncAttributeMaxDynamicSharedMemorySize, SMEM_SZ);
    cudaFuncSetAttribute(mma_layer<HH, 0, 0, 0>,
                         cudaFuncAttributeMaxDynamicSharedMemorySize, SMEM_SZ);

    prep_kernel<<<1, CC>>>(cat_ids);
    tau1_kernel<<<BB, 256>>>(timesteps);
    actconv_kernel<<<BB * TT * AA / 1024, 512>>>(actions);

    // weight planes (W2: lower half only; upper half stays fp32 for tau2)
    wconv_kernel<<<dim3(64, CC), 256>>>(W1, w1h, w1l,
        (size_t)AA * HH, (size_t)AA * HH, AA * HH / 2);
    wconv_kernel<<<dim3(64, CC), 256>>>(W2, w2h, w2l,
        (size_t)2 * HH * HH, (size_t)HH * HH, HH * HH / 2);
    wconv_kernel<<<dim3(64, CC), 256>>>(W3, w3h, w3l,
        (size_t)HH * HH, (size_t)HH * HH, HH * HH / 2);

    // layer 1: aemb planes = actions @ W1 + b1
    mma_layer<AA, 0, 0, 1><<<dim3(HH / NT, BB), 256, SMEM_SZ>>>(
        a0h, a0l, w1h, w1l, (size_t)AA * HH, b1, cat_ids, nullptr, a1h, a1l);

    // tau matvec: K-split partials + deterministic reduce
    tau2_kernel<<<dim3(HH / 2 / 128, CC, KSPLIT), 128>>>(W2);
    tau3_kernel<<<dim3(HH / 256, BB), 256>>>(cat_ids, b2);

    // layer 2: h planes = swish(aemb @ W2[:1024] + tauc)
    mma_layer<HH, 1, 1, 1><<<dim3(HH / NT, BB), 256, SMEM_SZ>>>(
        a1h, a1l, w2h, w2l, (size_t)HH * HH, tauc, cat_ids, nullptr, a2h, a2l);

    // layer 3: out fp32 = h @ W3 + b3
    mma_layer<HH, 0, 0, 0><<<dim3(HH / NT, BB), 256, SMEM_SZ>>>(
        a2h, a2l, w3h, w3l, (size_t)HH * HH, b3, cat_ids, out, nullptr, nullptr);
}

// round 14
// speedup vs baseline: 1.0061x; 1.0061x over previous
#include <cuda_runtime.h>
#include <cuda_bf16.h>
#include <math.h>
#include <stdint.h>

#define BB 64
#define TT 64
#define AA 64
#define HH 1024
#define CC 16

#define NT 128     // N cols per CTA
#define KC 32      // K floats per chunk

#define KSPLIT 32
#define TAU_KB (HH / KSPLIT)   // 32

// mma kernel dynamic smem layout (bytes)
#define A_PL   5120                    // 64 rows * 80 B
#define B_PL   8704                    // 32 rows * 272 B
#define BUF_SZ (2 * A_PL + 2 * B_PL)   // 27648
#define SMEM_SZ (2 * BUF_SZ)           // 55296

// Scratch (device globals; no runtime allocation)
__device__ __align__(16) __nv_bfloat16 g_a0h[BB * TT * AA], g_a0l[BB * TT * AA];
__device__ __align__(16) __nv_bfloat16 g_a1h[BB * TT * HH], g_a1l[BB * TT * HH];
__device__ __align__(16) __nv_bfloat16 g_a2h[BB * TT * HH], g_a2l[BB * TT * HH];
// Weight planes
__device__ __align__(16) __nv_bfloat16 g_w1h[CC * AA * HH], g_w1l[CC * AA * HH];
__device__ __align__(16) __nv_bfloat16 g_w2h[CC * HH * HH], g_w2l[CC * HH * HH];
__device__ __align__(16) __nv_bfloat16 g_w3h[CC * HH * HH], g_w3l[CC * HH * HH];
__device__ float g_tauc[BB * HH];
__device__ float g_tau[BB * HH];
__device__ float g_part[KSPLIT * BB * HH];
__device__ int   g_cat_cnt[CC];
__device__ int   g_cat_list[CC * BB];

// ---------------- helpers ----------------
__device__ __forceinline__ uint32_t smem_u32(const void* p) {
    uint32_t a;
    asm("{ .reg .u64 t; cvta.to.shared.u64 t, %1; cvt.u32.u64 %0, t; }"
        : "=r"(a) : "l"(p));
    return a;
}
__device__ __forceinline__ void split_pair(float x, float y, uint32_t& h, uint32_t& l) {
    __nv_bfloat162 hb = __floats2bfloat162_rn(x, y);   // low 16 = x
    float hx = __bfloat162float(hb.x);
    float hy = __bfloat162float(hb.y);
    __nv_bfloat162 lb = __floats2bfloat162_rn(x - hx, y - hy);
    h = *reinterpret_cast<uint32_t*>(&hb);
    l = *reinterpret_cast<uint32_t*>(&lb);
}
__device__ __forceinline__ void mma_bf16(float* c, const uint32_t* a, uint32_t b0, uint32_t b1) {
    asm volatile(
        "mma.sync.aligned.m16n8k16.row.col.f32.bf16.bf16.f32 "
        "{%0,%1,%2,%3}, {%4,%5,%6,%7}, {%8,%9}, {%0,%1,%2,%3};"
        : "+f"(c[0]), "+f"(c[1]), "+f"(c[2]), "+f"(c[3])
        : "r"(a[0]), "r"(a[1]), "r"(a[2]), "r"(a[3]), "r"(b0), "r"(b1));
}
__device__ __forceinline__ void ldsm_x4(uint32_t* r, uint32_t addr) {
    asm volatile("ldmatrix.sync.aligned.m8n8.x4.shared.b16 {%0,%1,%2,%3}, [%4];"
                 : "=r"(r[0]), "=r"(r[1]), "=r"(r[2]), "=r"(r[3]) : "r"(addr));
}
__device__ __forceinline__ void ldsm_x4_t(uint32_t* r, uint32_t addr) {
    asm volatile("ldmatrix.sync.aligned.m8n8.x4.trans.shared.b16 {%0,%1,%2,%3}, [%4];"
                 : "=r"(r[0]), "=r"(r[1]), "=r"(r[2]), "=r"(r[3]) : "r"(addr));
}
__device__ __forceinline__ void cp_async16(uint32_t s, const void* g) {
    asm volatile("cp.async.ca.shared.global [%0], [%1], 16;" :: "r"(s), "l"(g));
}
#define CP_COMMIT() asm volatile("cp.async.commit_group;" ::: "memory")
#define CP_WAIT(n)  asm volatile("cp.async.wait_group %0;" :: "n"(n) : "memory")

// ---------------------------------------------------------------------------
// prep: bucket batches by category (for tau2)
// ---------------------------------------------------------------------------
__global__ void prep_kernel(const int* __restrict__ cat_ids) {
    int c = threadIdx.x;
    if (c >= CC) return;
    int cnt = 0;
    for (int b = 0; b < BB; ++b)
        if (cat_ids[b] == c) g_cat_list[c * BB + cnt++] = b;
    g_cat_cnt[c] = cnt;
}

// ---------------------------------------------------------------------------
// wconv v2: fp32 weights -> bf16 hi/lo planes, streaming float4 loads.
// grid(nblk, CC), 256 thr; grid-stride over float4 quads.
// ---------------------------------------------------------------------------
__global__ void wconv_kernel(const float* __restrict__ src,
                             __nv_bfloat16* __restrict__ dh,
                             __nv_bfloat16* __restrict__ dl,
                             size_t src_cat_stride, size_t dst_cat_stride,
                             int nquads) {
    const int cat = blockIdx.y;
    const float4* s = (const float4*)(src + cat * src_cat_stride);
    uint2* oh = (uint2*)(dh + cat * dst_cat_stride);
    uint2* ol = (uint2*)(dl + cat * dst_cat_stride);
    const int stride = gridDim.x * 256;
    for (int i = blockIdx.x * 256 + threadIdx.x; i < nquads; i += stride) {
        float4 v = s[i];
        uint32_t h0, l0, h1, l1;
        split_pair(v.x, v.y, h0, l0);
        split_pair(v.z, v.w, h1, l1);
        oh[i] = make_uint2(h0, h1);
        ol[i] = make_uint2(l0, l1);
    }
}

// ---------------------------------------------------------------------------
// actconv: actions fp32 -> bf16 hi/lo planes
// ---------------------------------------------------------------------------
__global__ void actconv_kernel(const float* __restrict__ actions) {
    int i = blockIdx.x * 512 + threadIdx.x;    // pair index
    float x = actions[2 * i], y = actions[2 * i + 1];
    uint32_t h, l;
    split_pair(x, y, h, l);
    ((uint32_t*)g_a0h)[i] = h;
    ((uint32_t*)g_a0l)[i] = l;
}

// ---------------------------------------------------------------------------
// tau1: per-batch sinusoidal embedding vector (1024)
// ---------------------------------------------------------------------------
__global__ void tau1_kernel(const int* __restrict__ timesteps) {
    const int b = blockIdx.x;
    const int tid = threadIdx.x;
    const float t = (float)timesteps[b];
    const int half = HH / 2;
    const float scale = logf(10000.0f) / (float)half;
    for (int d = tid; d < HH; d += 256) {
        int j = (d < half) ? d : (d - half);
        float f = t * expf(-(float)j * scale);
        g_tau[b * HH + d] = (d < half) ? sinf(f) : cosf(f);
    }
}

// ---------------------------------------------------------------------------
// tau2: cat-grouped, K-split matvec partials
// grid(HH/2/128, CC, KSPLIT), 128 threads, float2 loads.
// ---------------------------------------------------------------------------
__global__ void tau2_kernel(const float* __restrict__ W2) {
    const int cat = blockIdx.y;
    const int z   = blockIdx.z;
    const int tid = threadIdx.x;
    const int n2  = blockIdx.x * 128 + tid;
    const int cnt = g_cat_cnt[cat];
    if (cnt == 0) return;

    __shared__ float ts[8][TAU_KB];
    const int k0 = z * TAU_KB;
    const float* Wp = W2 + (size_t)cat * 2 * HH * HH
                         + (size_t)(HH + k0) * HH + 2 * n2;

    for (int base = 0; base < cnt; base += 8) {
        int nb = min(8, cnt - base);
        __syncthreads();
        for (int bl = 0; bl < nb; ++bl) {
            int bb = g_cat_list[cat * BB + base + bl];
            for (int d = tid; d < TAU_KB; d += 128)
                ts[bl][d] = g_tau[bb * HH + k0 + d];
        }
        __syncthreads();
        float2 acc[8];
        #pragma unroll
        for (int bl = 0; bl < 8; ++bl) acc[bl] = make_float2(0.f, 0.f);
        #pragma unroll 4
        for (int k = 0; k < TAU_KB; ++k) {
            float2 w = *(const float2*)&Wp[(size_t)k * HH];
            #pragma unroll
            for (int bl = 0; bl < 8; ++bl) {
                acc[bl].x = fmaf(ts[bl][k], w.x, acc[bl].x);
                acc[bl].y = fmaf(ts[bl][k], w.y, acc[bl].y);
            }
        }
        for (int bl = 0; bl < nb; ++bl) {
            int bb = g_cat_list[cat * BB + base + bl];
            *(float2*)&g_part[((size_t)z * BB + bb) * HH + 2 * n2] = acc[bl];
        }
    }
}

// ---------------------------------------------------------------------------
// tau3: deterministic reduce of partials + bias -> g_tauc
// ---------------------------------------------------------------------------
__global__ void tau3_kernel(const int* __restrict__ cat_ids,
                            const float* __restrict__ b2) {
    const int b = blockIdx.y;
    const int n = blockIdx.x * 256 + threadIdx.x;
    const int c = cat_ids[b];
    float s = b2[c * HH + n];
    #pragma unroll
    for (int z = 0; z < KSPLIT; ++z)
        s += g_part[((size_t)z * BB + b) * HH + n];
    g_tauc[b * HH + n] = s;
}

// ---------------------------------------------------------------------------
// Split-bf16 mma.sync GEMM layer v2: all operands pre-split bf16 planes.
// Pure cp.async staging (no convert, no prefetch regs), double-buffered.
// grid(HH/NT, BB), 256 threads (2m x 4n warps, 32x32 each).
//   out[b] = act( A[b](64 x K) @ W[cat[b]](K x 1024) + addend )
// OUTMODE 0: fp32 out; OUTMODE 1: bf16 hi/lo planes.
// ---------------------------------------------------------------------------
template <int K, int ACT, int ADDMODE, int OUTMODE>
__global__ void __launch_bounds__(256, 3)
mma_layer(const __nv_bfloat16* __restrict__ Ahp,
          const __nv_bfloat16* __restrict__ Alp,
          const __nv_bfloat16* __restrict__ Whp,
          const __nv_bfloat16* __restrict__ Wlp,
          size_t wstride,
          const float* __restrict__ addv,
          const int* __restrict__ cat_ids,
          float* __restrict__ outf,
          __nv_bfloat16* __restrict__ outh,
          __nv_bfloat16* __restrict__ outl) {
    extern __shared__ char sm[];
    const uint32_t smb = smem_u32(sm);

    const int tid  = threadIdx.x;
    const int lane = tid & 31;
    const int warp = tid >> 5;
    const int wm   = warp >> 2;   // 0..1
    const int wn   = warp & 3;    // 0..3
    const int b    = blockIdx.y;
    const int nt   = blockIdx.x;
    const int c    = cat_ids[b];

    const __nv_bfloat16* Ap[2] = {Ahp + (size_t)b * 64 * K,
                                  Alp + (size_t)b * 64 * K};
    const __nv_bfloat16* Wp[2] = {Whp + (size_t)c * wstride + nt * NT,
                                  Wlp + (size_t)c * wstride + nt * NT};

    float acc[2][4][4];
    #pragma unroll
    for (int i = 0; i < 2; ++i)
        #pragma unroll
        for (int j = 0; j < 4; ++j)
            #pragma unroll
            for (int q = 0; q < 4; ++q) acc[i][j][q] = 0.0f;

    constexpr int NCHUNK = K / KC;

    // cp.async staging for one chunk into buffer `buf`:
    // A: 512 16B items (2 planes x 64 rows x 4/row): i = tid + 256r, r<2
    // B: 1024 16B items (2 planes x 32 rows x 16/row): i = tid + 256r, r<4
    auto issue = [&](int k0, int buf) {
        const uint32_t base = smb + buf * BUF_SZ;
        #pragma unroll
        for (int r = 0; r < 2; ++r) {
            int i = tid + r * 256;
            int p = i >> 8, rem = i & 255, m = rem >> 2, it = rem & 3;
            cp_async16(base + p * A_PL + m * 80 + it * 16,
                       Ap[p] + (size_t)m * K + k0 + it * 8);
        }
        #pragma unroll
        for (int r = 0; r < 4; ++r) {
            int i = tid + r * 256;
            int p = i >> 9, rem = i & 511, k = rem >> 4, it = rem & 15;
            cp_async16(base + 2 * A_PL + p * B_PL + k * 272 + it * 16,
                       Wp[p] + (size_t)(k0 + k) * HH + it * 8);
        }
    };

    const int l15 = lane & 15, g16 = lane >> 4;

    issue(0, 0); CP_COMMIT();

    for (int ch = 0; ch < NCHUNK; ++ch) {
        const int cur = ch & 1;
        if (ch + 1 < NCHUNK) {
            issue((ch + 1) * KC, cur ^ 1); CP_COMMIT();
            CP_WAIT(1);                    // chunk ch resident
        } else {
            CP_WAIT(0);
        }
        __syncthreads();

        // ---- MMA phase on buffer cur ----
        const uint32_t aHi = smb + cur * BUF_SZ;
        const uint32_t aLo = aHi + A_PL;
        const uint32_t bHi = aHi + 2 * A_PL;
        const uint32_t bLo = bHi + B_PL;
        #pragma unroll
        for (int t = 0; t < 2; ++t) {
            uint32_t Ahf[2][4], Alf[2][4];
            #pragma unroll
            for (int ms = 0; ms < 2; ++ms) {
                uint32_t abyte = (wm * 32 + ms * 16 + l15) * 80 + t * 32 + g16 * 16;
                ldsm_x4(Ahf[ms], aHi + abyte);
                ldsm_x4(Alf[ms], aLo + abyte);
            }
            uint32_t Bh[2][4], Bl[2][4];
            #pragma unroll
            for (int nfp = 0; nfp < 2; ++nfp) {
                int kr = t * 16 + l15;
                uint32_t bbyte = kr * 272 + (wn * 32 + nfp * 16 + g16 * 8) * 2;
                ldsm_x4_t(Bh[nfp], bHi + bbyte);
                ldsm_x4_t(Bl[nfp], bLo + bbyte);
            }
            #pragma unroll
            for (int nf = 0; nf < 4; ++nf) {
                uint32_t bh0 = Bh[nf >> 1][(nf & 1) * 2];
                uint32_t bh1 = Bh[nf >> 1][(nf & 1) * 2 + 1];
                uint32_t bl0 = Bl[nf >> 1][(nf & 1) * 2];
                uint32_t bl1 = Bl[nf >> 1][(nf & 1) * 2 + 1];
                #pragma unroll
                for (int ms = 0; ms < 2; ++ms) {
                    mma_bf16(acc[ms][nf], Ahf[ms], bh0, bh1);   // hi*hi
                    mma_bf16(acc[ms][nf], Ahf[ms], bl0, bl1);   // hi*lo
                    mma_bf16(acc[ms][nf], Alf[ms], bh0, bh1);   // lo*hi
                }
            }
        }
        __syncthreads();   // all warps done reading buffer cur
    }

    // ---- epilogue ----
    const float* addp = (ADDMODE == 0) ? (addv + (size_t)c * HH)
                                       : (addv + (size_t)b * HH);
    const int lr = lane >> 2;
    const int lc = lane & 3;
    #pragma unroll
    for (int ms = 0; ms < 2; ++ms) {
        int r0 = wm * 32 + ms * 16 + lr;
        #pragma unroll
        for (int nf = 0; nf < 4; ++nf) {
            int ncol = nt * NT + wn * 32 + nf * 8 + lc * 2;
            float bv0 = addp[ncol], bv1 = addp[ncol + 1];
            float v0 = acc[ms][nf][0] + bv0;
            float v1 = acc[ms][nf][1] + bv1;
            float v2 = acc[ms][nf][2] + bv0;
            float v3 = acc[ms][nf][3] + bv1;
            if (ACT == 1) {
                v0 = v0 / (1.0f + expf(-v0));
                v1 = v1 / (1.0f + expf(-v1));
                v2 = v2 / (1.0f + expf(-v2));
                v3 = v3 / (1.0f + expf(-v3));
            }
            size_t o0 = ((size_t)b * TT + r0)     * HH + ncol;
            size_t o1 = ((size_t)b * TT + r0 + 8) * HH + ncol;
            if (OUTMODE == 0) {
                *(float2*)&outf[o0] = make_float2(v0, v1);
                *(float2*)&outf[o1] = make_float2(v2, v3);
            } else {
                uint32_t h, l;
                split_pair(v0, v1, h, l);
                *(uint32_t*)&outh[o0] = h;
                *(uint32_t*)&outl[o0] = l;
                split_pair(v2, v3, h, l);
                *(uint32_t*)&outh[o1] = h;
                *(uint32_t*)&outl[o1] = l;
            }
        }
    }
}

extern "C" void kernel_launch(void* const* d_in, const int* in_sizes, int n_in,
                              void* d_out, int out_size) {
    const float* actions   = (const float*)d_in[0];
    const int*   timesteps = (const int*)d_in[1];
    const int*   cat_ids   = (const int*)d_in[2];
    const float* W1 = (const float*)d_in[3];
    const float* b1 = (const float*)d_in[4];
    const float* W2 = (const float*)d_in[5];
    const float* b2 = (const float*)d_in[6];
    const float* W3 = (const float*)d_in[7];
    const float* b3 = (const float*)d_in[8];
    float* out = (float*)d_out;

    __nv_bfloat16 *a0h, *a0l, *a1h, *a1l, *a2h, *a2l;
    __nv_bfloat16 *w1h, *w1l, *w2h, *w2l, *w3h, *w3l;
    float *tauc;
    cudaGetSymbolAddress((void**)&a0h, g_a0h);
    cudaGetSymbolAddress((void**)&a0l, g_a0l);
    cudaGetSymbolAddress((void**)&a1h, g_a1h);
    cudaGetSymbolAddress((void**)&a1l, g_a1l);
    cudaGetSymbolAddress((void**)&a2h, g_a2h);
    cudaGetSymbolAddress((void**)&a2l, g_a2l);
    cudaGetSymbolAddress((void**)&w1h, g_w1h);
    cudaGetSymbolAddress((void**)&w1l, g_w1l);
    cudaGetSymbolAddress((void**)&w2h, g_w2h);
    cudaGetSymbolAddress((void**)&w2l, g_w2l);
    cudaGetSymbolAddress((void**)&w3h, g_w3h);
    cudaGetSymbolAddress((void**)&w3l, g_w3l);
    cudaGetSymbolAddress((void**)&tauc, g_tauc);

    cudaFuncSetAttribute(mma_layer<AA, 0, 0, 1>,
                         cudaFuncAttributeMaxDynamicSharedMemorySize, SMEM_SZ);
    cudaFuncSetAttribute(mma_layer<HH, 1, 1, 1>,
                         cudaFuncAttributeMaxDynamicSharedMemorySize, SMEM_SZ);
    cudaFuncSetAttribute(mma_layer<HH, 0, 0, 0>,
                         cudaFuncAttributeMaxDynamicSharedMemorySize, SMEM_SZ);

    prep_kernel<<<1, CC>>>(cat_ids);
    tau1_kernel<<<BB, 256>>>(timesteps);
    actconv_kernel<<<BB * TT * AA / 1024, 512>>>(actions);

    // weight planes (W2: lower half only; upper half stays fp32 for tau2)
    wconv_kernel<<<dim3(16, CC), 256>>>(W1, w1h, w1l,
        (size_t)AA * HH, (size_t)AA * HH, AA * HH / 4);
    wconv_kernel<<<dim3(128, CC), 256>>>(W2, w2h, w2l,
        (size_t)2 * HH * HH, (size_t)HH * HH, HH * HH / 4);
    wconv_kernel<<<dim3(128, CC), 256>>>(W3, w3h, w3l,
        (size_t)HH * HH, (size_t)HH * HH, HH * HH / 4);

    // layer 1: aemb planes = actions @ W1 + b1
    mma_layer<AA, 0, 0, 1><<<dim3(HH / NT, BB), 256, SMEM_SZ>>>(
        a0h, a0l, w1h, w1l, (size_t)AA * HH, b1, cat_ids, nullptr, a1h, a1l);

    // tau matvec: K-split partials + deterministic reduce
    tau2_kernel<<<dim3(HH / 2 / 128, CC, KSPLIT), 128>>>(W2);
    tau3_kernel<<<dim3(HH / 256, BB), 256>>>(cat_ids, b2);

    // layer 2: h planes = swish(aemb @ W2[:1024] + tauc)
    mma_layer<HH, 1, 1, 1><<<dim3(HH / NT, BB), 256, SMEM_SZ>>>(
        a1h, a1l, w2h, w2l, (size_t)HH * HH, tauc, cat_ids, nullptr, a2h, a2l);

    // layer 3: out fp32 = h @ W3 + b3
    mma_layer<HH, 0, 0, 0><<<dim3(HH / NT, BB), 256, SMEM_SZ>>>(
        a2h, a2l, w3h, w3l, (size_t)HH * HH, b3, cat_ids, out, nullptr, nullptr);
}